// round 1
// baseline (speedup 1.0000x reference)
#include <cuda_runtime.h>

// Shapes fixed by the dataset
#define NN   8192
#define D    128
#define PP   256
#define KK   256
#define DEGN 32
#define FFN  16
#define TEMP_INV (1.0f/0.07f)

// Scratch (no allocations allowed)
__device__ float g_zq[D];            // normalized z[query]
__device__ float g_znx[DEGN * D];    // normalized z[N(q)]
__device__ float g_te[DEGN];         // time encodings for query neighborhood
__device__ float g_core_sum;         // sum (core[nb]-core[q])^2
__device__ float g_pos[PP];
__device__ float g_align[PP];
__device__ float g_neg[KK];

__device__ __forceinline__ float warpSum(float v) {
#pragma unroll
    for (int o = 16; o; o >>= 1) v += __shfl_xor_sync(0xffffffffu, v, o);
    return v;
}

// ---------------------------------------------------------------------------
// k0: query-side precompute (1 block x 256 threads)
// ---------------------------------------------------------------------------
__global__ void k0_setup(const float* __restrict__ z,
                         const float* __restrict__ edge_times,
                         const float* __restrict__ cur_t,
                         const float* __restrict__ core,
                         const float* __restrict__ omega,
                         const float* __restrict__ phi,
                         const int*   __restrict__ qidx,
                         const int*   __restrict__ nbr_idxs,
                         const int*   __restrict__ neighbors)
{
    __shared__ float red[8];
    __shared__ float s_inv;
    const int tid = threadIdx.x;
    const int lane = tid & 31, warp = tid >> 5;
    const int q = qidx[0];
    const float ct = cur_t[0];

    // --- normalize z_q (dims owned by tid < 128) ---
    float v = (tid < D) ? z[q * D + tid] : 0.f;
    {
        float s = warpSum(v * v);
        if (lane == 0) red[warp] = s;
        __syncthreads();
        if (tid == 0) {
            float t = 0.f;
            for (int i = 0; i < 8; i++) t += red[i];
            s_inv = 1.f / fmaxf(sqrtf(t), 1e-12f);
        }
        __syncthreads();
        if (tid < D) g_zq[tid] = v * s_inv;
    }

    // --- normalize the DEG rows of z[N(q)] ---
    for (int j = 0; j < DEGN; j++) {
        int idx = neighbors[q * DEGN + j];
        float w = (tid < D) ? z[idx * D + tid] : 0.f;
        float ss = warpSum(w * w);
        __syncthreads();                    // protect red / s_inv reuse
        if (lane == 0) red[warp] = ss;
        __syncthreads();
        if (tid == 0) {
            float t = 0.f;
            for (int i = 0; i < 8; i++) t += red[i];
            s_inv = 1.f / fmaxf(sqrtf(t), 1e-12f);
        }
        __syncthreads();
        if (tid < D) g_znx[j * D + tid] = w * s_inv;
    }

    // --- time encodings for query neighborhood (threads 0..31) ---
    if (tid < DEGN) {
        int idx = neighbors[q * DEGN + tid];
        float dt = ct - edge_times[(long long)q * NN + idx];
        float te = omega[0] * dt + phi[0];
#pragma unroll
        for (int f = 1; f < FFN; f++) te += sinf(omega[f] * dt + phi[f]);
        g_te[tid] = te;
    }

    // --- core proximity sum over P (all 256 threads) ---
    {
        float cq = core[q];
        float cd = core[nbr_idxs[tid]] - cq;
        float cs = warpSum(cd * cd);
        __syncthreads();
        if (lane == 0) red[warp] = cs;
        __syncthreads();
        if (tid == 0) {
            float t = 0.f;
            for (int i = 0; i < 8; i++) t += red[i];
            g_core_sum = t;
        }
    }
}

// ---------------------------------------------------------------------------
// k1: main per-neighbor + per-negative work (P+K blocks x 128 threads)
// ---------------------------------------------------------------------------
__global__ void __launch_bounds__(128)
k1_main(const float* __restrict__ z,
        const float* __restrict__ edge_times,
        const float* __restrict__ cur_t,
        const float* __restrict__ omega,
        const float* __restrict__ phi,
        const int*   __restrict__ neg_idxs,
        const int*   __restrict__ nbr_idxs,
        const int*   __restrict__ neighbors)
{
    __shared__ float s_zq[D];
    __shared__ float s_te[DEGN];
    __shared__ float s_om[FFN], s_ph[FFN];
    __shared__ float red[4];
    __shared__ float s_znb[D];
    __shared__ float s_acc[4][4];

    const int tid = threadIdx.x;
    const int lane = tid & 31, warp = tid >> 5;
    const int b = blockIdx.x;
    const float ct = cur_t[0];

    if (tid < D)   s_zq[tid] = g_zq[tid];
    if (tid < DEGN) s_te[tid] = g_te[tid];
    if (tid < FFN) { s_om[tid] = omega[tid]; s_ph[tid] = phi[tid]; }
    __syncthreads();

    if (b < PP) {
        const int p = b;
        const int nbp = nbr_idxs[p];

        // normalize z_nb; tid owns dim tid
        float v = z[(long long)nbp * D + tid];
        float ss = warpSum(v * v);
        if (lane == 0) red[warp] = ss;
        __syncthreads();
        float inv = 1.f / fmaxf(sqrtf(red[0] + red[1] + red[2] + red[3]), 1e-12f);
        float znb = v * inv;

        // mu_xy
        float dq = znb - s_zq[tid];
        float ds = warpSum(dq * dq);
        __syncthreads();
        if (lane == 0) red[warp] = ds;
        s_znb[tid] = znb;
        __syncthreads();
        float muxy = -(red[0] + red[1] + red[2] + red[3]);

        // lane-owned float4 slices (same dims for every warp)
        float4 znb4 = *(const float4*)&s_znb[lane * 4];
        float4 zq4  = *(const float4*)&s_zq[lane * 4];

        float aw1 = 0.f, awm1 = 0.f, aw2 = 0.f, awm2 = 0.f;
        for (int j = warp; j < DEGN; j += 4) {
            // ---- term1: attention over N(q) ----
            float4 x = *(const float4*)&g_znx[j * D + lane * 4];
            float d0 = x.x - znb4.x, d1 = x.y - znb4.y;
            float d2 = x.z - znb4.z, d3 = x.w - znb4.w;
            float mu1 = -warpSum(d0 * d0 + d1 * d1 + d2 * d2 + d3 * d3);
            float w1 = expf(mu1 * TEMP_INV - s_te[j]);
            aw1 += w1; awm1 += w1 * mu1;

            // ---- term2: attention over N(y_p) ----
            int idx = neighbors[nbp * DEGN + j];
            float4 r = ((const float4*)(z + (long long)idx * D))[lane];
            float ss2 = warpSum(r.x * r.x + r.y * r.y + r.z * r.z + r.w * r.w);
            float inv2 = 1.f / fmaxf(sqrtf(ss2), 1e-12f);
            float e0 = r.x * inv2 - zq4.x, e1 = r.y * inv2 - zq4.y;
            float e2 = r.z * inv2 - zq4.z, e3 = r.w * inv2 - zq4.w;
            float mu2 = -warpSum(e0 * e0 + e1 * e1 + e2 * e2 + e3 * e3);

            float dt = ct - edge_times[(long long)nbp * NN + idx];
            float c;
            if (lane == 0)        c = s_om[0] * dt + s_ph[0];
            else if (lane < FFN)  c = sinf(s_om[lane] * dt + s_ph[lane]);
            else                  c = 0.f;
            float te = warpSum(c);
            float w2 = expf(mu2 * TEMP_INV - te);
            aw2 += w2; awm2 += w2 * mu2;
        }
        if (lane == 0) {
            s_acc[warp][0] = aw1; s_acc[warp][1] = awm1;
            s_acc[warp][2] = aw2; s_acc[warp][3] = awm2;
        }
        __syncthreads();
        if (tid == 0) {
            float W1 = 0, WM1 = 0, W2 = 0, WM2 = 0;
            for (int w = 0; w < 4; w++) {
                W1 += s_acc[w][0]; WM1 += s_acc[w][1];
                W2 += s_acc[w][2]; WM2 += s_acc[w][3];
            }
            float term1 = WM1 / (W1 + 1e-8f);
            float term2 = WM2 / (W2 + 1e-8f);
            float d = term1 + term2;               // lambda_T - lambda_S
            float ad = fabsf(d);
            g_align[p] = (ad < 1.f) ? 0.5f * d * d : ad - 0.5f;
            float sgm = 1.f / (1.f + expf(-muxy));
            g_pos[p] = -logf(sgm + 1e-8f);
        }
    } else {
        // negative sample block
        const int k = b - PP;
        const int idx = neg_idxs[k];
        float v = z[(long long)idx * D + tid];
        float ss = warpSum(v * v);
        if (lane == 0) red[warp] = ss;
        __syncthreads();
        float inv = 1.f / fmaxf(sqrtf(red[0] + red[1] + red[2] + red[3]), 1e-12f);
        float d = v * inv - s_zq[tid];
        float ds = warpSum(d * d);
        __syncthreads();
        if (lane == 0) red[warp] = ds;
        __syncthreads();
        if (tid == 0) {
            float mu = -(red[0] + red[1] + red[2] + red[3]);
            float sgm = 1.f / (1.f + expf(-mu));
            g_neg[k] = -logf(1.f - sgm + 1e-8f);
        }
    }
}

// ---------------------------------------------------------------------------
// k2: final deterministic reduction (1 block x 256 threads)
// ---------------------------------------------------------------------------
__global__ void k2_fin(float* __restrict__ out)
{
    __shared__ float rp[8], rn[8], ra[8];
    const int tid = threadIdx.x;
    const int lane = tid & 31, warp = tid >> 5;

    float a = warpSum(g_pos[tid]);
    float n = warpSum(g_neg[tid]);
    float c = warpSum(g_align[tid]);
    if (lane == 0) { rp[warp] = a; rn[warp] = n; ra[warp] = c; }
    __syncthreads();
    if (tid == 0) {
        float P = 0, Ng = 0, A = 0;
        for (int i = 0; i < 8; i++) { P += rp[i]; Ng += rn[i]; A += ra[i]; }
        float tightness = P / PP + Ng / KK;
        float loss = tightness + 0.1f * (g_core_sum / PP) + 0.1f * (A / PP);
        out[0] = loss;
    }
}

// ---------------------------------------------------------------------------
extern "C" void kernel_launch(void* const* d_in, const int* in_sizes, int n_in,
                              void* d_out, int out_size)
{
    const float* z          = (const float*)d_in[0];
    const float* edge_times = (const float*)d_in[1];
    const float* cur_t      = (const float*)d_in[2];
    const float* core       = (const float*)d_in[3];
    const float* omega      = (const float*)d_in[4];
    const float* phi        = (const float*)d_in[5];
    const int*   qidx       = (const int*)d_in[6];
    const int*   neg_idxs   = (const int*)d_in[7];
    const int*   nbr_idxs   = (const int*)d_in[8];
    const int*   neighbors  = (const int*)d_in[9];

    k0_setup<<<1, 256>>>(z, edge_times, cur_t, core, omega, phi,
                         qidx, nbr_idxs, neighbors);
    k1_main<<<PP + KK, 128>>>(z, edge_times, cur_t, omega, phi,
                              neg_idxs, nbr_idxs, neighbors);
    k2_fin<<<1, 256>>>((float*)d_out);
}

// round 2
// speedup vs baseline: 1.9734x; 1.9734x over previous
#include <cuda_runtime.h>

// Shapes fixed by the dataset
#define NN   8192
#define D    128
#define PP   256
#define KK   256
#define DEGN 32
#define FFN  16
#define TEMP_INV (1.0f/0.07f)

// Scratch (no allocations allowed)
__device__ __align__(16) float g_zq[D];          // normalized z[query]
__device__ __align__(16) float g_znx[DEGN * D];  // normalized z[N(q)]
__device__ float g_te[DEGN];          // time encodings for query neighborhood
__device__ float g_core_sum;          // sum (core[nb]-core[q])^2
__device__ float g_pos[PP];
__device__ float g_align_arr[PP];
__device__ float g_neg[KK];
__device__ unsigned int g_ctr;        // last-block counter (reset by k0)

__device__ __forceinline__ float warpSum(float v) {
#pragma unroll
    for (int o = 16; o; o >>= 1) v += __shfl_xor_sync(0xffffffffu, v, o);
    return v;
}

// ---------------------------------------------------------------------------
// k0: query-side precompute, fully warp-parallel (1 block x 1024 threads)
//   warp w : normalize z[N(q)[w]] -> g_znx row w, compute g_te[w]
//   warp 0 : additionally normalizes z_q
//   warps 0-7 : core proximity sum
// ---------------------------------------------------------------------------
__global__ void __launch_bounds__(1024) k0_setup(
        const float* __restrict__ z,
        const float* __restrict__ edge_times,
        const float* __restrict__ cur_t,
        const float* __restrict__ core,
        const float* __restrict__ omega,
        const float* __restrict__ phi,
        const int*   __restrict__ qidx,
        const int*   __restrict__ nbr_idxs,
        const int*   __restrict__ neighbors)
{
    __shared__ float red[32];
    const int tid = threadIdx.x;
    const int lane = tid & 31, warp = tid >> 5;
    const int q = qidx[0];
    const float ct = cur_t[0];

    if (tid == 0) g_ctr = 0;   // reset last-block counter for this launch

    // warp 0: normalize z_q
    if (warp == 0) {
        float4 v = ((const float4*)(z + (size_t)q * D))[lane];
        float ss = warpSum(v.x*v.x + v.y*v.y + v.z*v.z + v.w*v.w);
        float inv = 1.f / fmaxf(sqrtf(ss), 1e-12f);
        ((float4*)g_zq)[lane] = make_float4(v.x*inv, v.y*inv, v.z*inv, v.w*inv);
    }

    // warp w: normalize row N(q)[w]
    const int idx = neighbors[q * DEGN + warp];            // broadcast
    {
        float4 r = ((const float4*)(z + (size_t)idx * D))[lane];
        float ss = warpSum(r.x*r.x + r.y*r.y + r.z*r.z + r.w*r.w);
        float inv = 1.f / fmaxf(sqrtf(ss), 1e-12f);
        ((float4*)g_znx)[warp * 32 + lane] =
            make_float4(r.x*inv, r.y*inv, r.z*inv, r.w*inv);
    }

    // warp w: time encoding te[w], lane-parallel sinusoids
    {
        float dt = 0.f;
        if (lane == 0) dt = ct - edge_times[(size_t)q * NN + idx];
        dt = __shfl_sync(0xffffffffu, dt, 0);
        float c = 0.f;
        if (lane == 0)       c = omega[0] * dt + phi[0];
        else if (lane < FFN) c = sinf(omega[lane] * dt + phi[lane]);
        float te = warpSum(c);
        if (lane == 0) g_te[warp] = te;
    }

    // core proximity sum over P (threads 0..255)
    {
        float cd = 0.f;
        if (tid < PP) cd = core[nbr_idxs[tid]] - core[q];
        float cs = warpSum(cd * cd);
        if (lane == 0) red[warp] = cs;
        __syncthreads();
        if (tid == 0) {
            float t = 0.f;
            for (int i = 0; i < 8; i++) t += red[i];
            g_core_sum = t;
        }
    }
}

// ---------------------------------------------------------------------------
// k1: per-neighbor + per-negative work (P+K blocks x 128 threads),
//     last block folds the final reduction (threadfence pattern).
// Uses mu(a,b) = 2*(a.b) - 2 for unit vectors -> independent butterflies.
// ---------------------------------------------------------------------------
__global__ void __launch_bounds__(128)
k1_main(const float* __restrict__ z,
        const float* __restrict__ edge_times,
        const float* __restrict__ cur_t,
        const float* __restrict__ omega,
        const float* __restrict__ phi,
        const int*   __restrict__ neg_idxs,
        const int*   __restrict__ nbr_idxs,
        const int*   __restrict__ neighbors,
        float* __restrict__ out)
{
    __shared__ __align__(16) float s_zq[D];
    __shared__ __align__(16) float s_znb[D];
    __shared__ float s_te[DEGN];
    __shared__ float s_om[FFN], s_ph[FFN];
    __shared__ float red2[4][2];
    __shared__ float s_acc[4][4];
    __shared__ float fr[12];
    __shared__ unsigned int s_islast;

    const int tid = threadIdx.x;
    const int lane = tid & 31, warp = tid >> 5;
    const int b = blockIdx.x;
    const float ct = cur_t[0];

    if (tid < D)    s_zq[tid] = g_zq[tid];
    if (tid < DEGN) s_te[tid] = g_te[tid];
    if (tid < FFN)  { s_om[tid] = omega[tid]; s_ph[tid] = phi[tid]; }
    __syncthreads();

    if (b < PP) {
        const int p = b;
        const int nbp = nbr_idxs[p];

        // normalize z_nb and mu_xy via two independent reductions
        float v  = z[(size_t)nbp * D + tid];
        float zq = s_zq[tid];
        float ss = warpSum(v * v);
        float dp = warpSum(v * zq);
        if (lane == 0) { red2[warp][0] = ss; red2[warp][1] = dp; }
        __syncthreads();
        float SS = red2[0][0] + red2[1][0] + red2[2][0] + red2[3][0];
        float DP = red2[0][1] + red2[1][1] + red2[2][1] + red2[3][1];
        float inv = 1.f / fmaxf(sqrtf(SS), 1e-12f);
        float muxy = 2.f * DP * inv - 2.f;
        s_znb[tid] = v * inv;
        __syncthreads();

        float4 znb4 = ((const float4*)s_znb)[lane];
        float4 zq4  = ((const float4*)s_zq)[lane];

        // prefetch this warp's 8 neighbor indices + edge times
        int   jidx = 0; float jet = 0.f;
        if (lane < 8) {
            jidx = neighbors[nbp * DEGN + warp + 4 * lane];
            jet  = edge_times[(size_t)nbp * NN + jidx];
        }

        float aw1 = 0.f, awm1 = 0.f, aw2 = 0.f, awm2 = 0.f;
#pragma unroll
        for (int i = 0; i < 8; i++) {
            const int j = warp + 4 * i;
            const int idx = __shfl_sync(0xffffffffu, jidx, i);
            const float dt = ct - __shfl_sync(0xffffffffu, jet, i);

            float4 x = ((const float4*)g_znx)[j * 32 + lane];
            float dot1 = x.x*znb4.x + x.y*znb4.y + x.z*znb4.z + x.w*znb4.w;

            float4 r = ((const float4*)(z + (size_t)idx * D))[lane];
            float ss2  = r.x*r.x + r.y*r.y + r.z*r.z + r.w*r.w;
            float dot2 = r.x*zq4.x + r.y*zq4.y + r.z*zq4.z + r.w*zq4.w;

            float c = 0.f;
            if (lane == 0)       c = s_om[0] * dt + s_ph[0];
            else if (lane < FFN) c = sinf(s_om[lane] * dt + s_ph[lane]);

            // four independent butterflies (ILP-overlapped)
            dot1 = warpSum(dot1);
            ss2  = warpSum(ss2);
            dot2 = warpSum(dot2);
            float te = warpSum(c);

            float mu1 = 2.f * dot1 - 2.f;
            float w1  = expf(mu1 * TEMP_INV - s_te[j]);
            aw1 += w1; awm1 += w1 * mu1;

            float inv2 = 1.f / fmaxf(sqrtf(ss2), 1e-12f);
            float mu2  = 2.f * dot2 * inv2 - 2.f;
            float w2   = expf(mu2 * TEMP_INV - te);
            aw2 += w2; awm2 += w2 * mu2;
        }
        if (lane == 0) {
            s_acc[warp][0] = aw1; s_acc[warp][1] = awm1;
            s_acc[warp][2] = aw2; s_acc[warp][3] = awm2;
        }
        __syncthreads();
        if (tid == 0) {
            float W1 = 0, WM1 = 0, W2 = 0, WM2 = 0;
            for (int w = 0; w < 4; w++) {
                W1 += s_acc[w][0]; WM1 += s_acc[w][1];
                W2 += s_acc[w][2]; WM2 += s_acc[w][3];
            }
            float term1 = WM1 / (W1 + 1e-8f);
            float term2 = WM2 / (W2 + 1e-8f);
            float d = term1 + term2;             // lambda_T - lambda_S
            float ad = fabsf(d);
            g_align_arr[p] = (ad < 1.f) ? 0.5f * d * d : ad - 0.5f;
            float sgm = 1.f / (1.f + expf(-muxy));
            g_pos[p] = -logf(sgm + 1e-8f);
        }
    } else {
        // negative sample block
        const int k = b - PP;
        const int idx = neg_idxs[k];
        float v  = z[(size_t)idx * D + tid];
        float zq = s_zq[tid];
        float ss = warpSum(v * v);
        float dp = warpSum(v * zq);
        if (lane == 0) { red2[warp][0] = ss; red2[warp][1] = dp; }
        __syncthreads();
        if (tid == 0) {
            float SS = red2[0][0] + red2[1][0] + red2[2][0] + red2[3][0];
            float DP = red2[0][1] + red2[1][1] + red2[2][1] + red2[3][1];
            float inv = 1.f / fmaxf(sqrtf(SS), 1e-12f);
            float mu  = 2.f * DP * inv - 2.f;
            float sgm = 1.f / (1.f + expf(-mu));
            g_neg[k] = -logf(1.f - sgm + 1e-8f);
        }
    }

    // ---- last-block final reduction (deterministic) ----
    __syncthreads();
    if (tid == 0) {
        __threadfence();
        unsigned int t = atomicAdd(&g_ctr, 1u);
        s_islast = (t == (unsigned int)(gridDim.x - 1));
    }
    __syncthreads();
    if (s_islast) {
        float sp = 0.f, sn = 0.f, sa = 0.f;
        for (int i = tid; i < PP; i += 128) { sp += g_pos[i]; sa += g_align_arr[i]; }
        for (int i = tid; i < KK; i += 128) sn += g_neg[i];
        sp = warpSum(sp); sn = warpSum(sn); sa = warpSum(sa);
        if (lane == 0) { fr[warp] = sp; fr[4 + warp] = sn; fr[8 + warp] = sa; }
        __syncthreads();
        if (tid == 0) {
            float P  = fr[0] + fr[1] + fr[2] + fr[3];
            float Ng = fr[4] + fr[5] + fr[6] + fr[7];
            float A  = fr[8] + fr[9] + fr[10] + fr[11];
            out[0] = P / PP + Ng / KK
                   + 0.1f * (g_core_sum / PP)
                   + 0.1f * (A / PP);
        }
    }
}

// ---------------------------------------------------------------------------
extern "C" void kernel_launch(void* const* d_in, const int* in_sizes, int n_in,
                              void* d_out, int out_size)
{
    const float* z          = (const float*)d_in[0];
    const float* edge_times = (const float*)d_in[1];
    const float* cur_t      = (const float*)d_in[2];
    const float* core       = (const float*)d_in[3];
    const float* omega      = (const float*)d_in[4];
    const float* phi        = (const float*)d_in[5];
    const int*   qidx       = (const int*)d_in[6];
    const int*   neg_idxs   = (const int*)d_in[7];
    const int*   nbr_idxs   = (const int*)d_in[8];
    const int*   neighbors  = (const int*)d_in[9];

    k0_setup<<<1, 1024>>>(z, edge_times, cur_t, core, omega, phi,
                          qidx, nbr_idxs, neighbors);
    k1_main<<<PP + KK, 128>>>(z, edge_times, cur_t, omega, phi,
                              neg_idxs, nbr_idxs, neighbors, (float*)d_out);
}

// round 3
// speedup vs baseline: 2.2462x; 1.1382x over previous
#include <cuda_runtime.h>

// Shapes fixed by the dataset
#define NN   8192
#define D    128
#define PP   256
#define KK   256
#define DEGN 32
#define FFN  16
#define TEMP_INV (1.0f/0.07f)
#define NEG_BLOCKS (KK / 8)
#define GRID (PP + NEG_BLOCKS)

// Scratch (no allocations allowed)
__device__ __align__(16) float g_zq[D];          // normalized z[query]
__device__ __align__(16) float g_znx[DEGN * D];  // normalized z[N(q)]
__device__ float g_te[DEGN];          // time encodings for query neighborhood
__device__ float g_core_sum;          // sum (core[nb]-core[q])^2
__device__ float g_pos[PP];
__device__ float g_align_arr[PP];
__device__ float g_neg[KK];
__device__ unsigned int g_ctr;        // last-block counter (reset by k0)

__device__ __forceinline__ float warpSum(float v) {
#pragma unroll
    for (int o = 16; o; o >>= 1) v += __shfl_xor_sync(0xffffffffu, v, o);
    return v;
}

// ---------------------------------------------------------------------------
// k0: query-side precompute, fully warp-parallel (1 block x 1024 threads)
// ---------------------------------------------------------------------------
__global__ void __launch_bounds__(1024) k0_setup(
        const float* __restrict__ z,
        const float* __restrict__ edge_times,
        const float* __restrict__ cur_t,
        const float* __restrict__ core,
        const float* __restrict__ omega,
        const float* __restrict__ phi,
        const int*   __restrict__ qidx,
        const int*   __restrict__ nbr_idxs,
        const int*   __restrict__ neighbors)
{
    __shared__ float red[32];
    const int tid = threadIdx.x;
    const int lane = tid & 31, warp = tid >> 5;
    const int q = qidx[0];
    const float ct = cur_t[0];

    if (tid == 0) g_ctr = 0;   // reset last-block counter for this launch

    // warp 0: normalize z_q
    if (warp == 0) {
        float4 v = ((const float4*)(z + (size_t)q * D))[lane];
        float ss = warpSum(v.x*v.x + v.y*v.y + v.z*v.z + v.w*v.w);
        float inv = 1.f / fmaxf(sqrtf(ss), 1e-12f);
        ((float4*)g_zq)[lane] = make_float4(v.x*inv, v.y*inv, v.z*inv, v.w*inv);
    }

    // warp w: normalize row N(q)[w]
    const int idx = neighbors[q * DEGN + warp];            // broadcast
    {
        float4 r = ((const float4*)(z + (size_t)idx * D))[lane];
        float ss = warpSum(r.x*r.x + r.y*r.y + r.z*r.z + r.w*r.w);
        float inv = 1.f / fmaxf(sqrtf(ss), 1e-12f);
        ((float4*)g_znx)[warp * 32 + lane] =
            make_float4(r.x*inv, r.y*inv, r.z*inv, r.w*inv);
    }

    // warp w: time encoding te[w]
    {
        float dt = 0.f;
        if (lane == 0) dt = ct - edge_times[(size_t)q * NN + idx];
        dt = __shfl_sync(0xffffffffu, dt, 0);
        float c = 0.f;
        if (lane == 0)       c = omega[0] * dt + phi[0];
        else if (lane < FFN) c = sinf(omega[lane] * dt + phi[lane]);
        float te = warpSum(c);
        if (lane == 0) g_te[warp] = te;
    }

    // core proximity sum over P (threads 0..255)
    {
        float cd = 0.f;
        if (tid < PP) cd = core[nbr_idxs[tid]] - core[q];
        float cs = warpSum(cd * cd);
        if (lane == 0) red[warp] = cs;
        __syncthreads();
        if (tid == 0) {
            float t = 0.f;
            for (int i = 0; i < 8; i++) t += red[i];
            g_core_sum = t;
        }
    }
}

// ---------------------------------------------------------------------------
// k1: one warp per (p, j).  Term blocks: b < PP, 32 warps = 32 neighbors.
//     Neg blocks: 8 negatives per block (128-thread groups).
//     Last block folds the final scalar reduction.
// ---------------------------------------------------------------------------
__global__ void __launch_bounds__(1024, 2)
k1_main(const float* __restrict__ z,
        const float* __restrict__ edge_times,
        const float* __restrict__ cur_t,
        const float* __restrict__ omega,
        const float* __restrict__ phi,
        const int*   __restrict__ neg_idxs,
        const int*   __restrict__ nbr_idxs,
        const int*   __restrict__ neighbors,
        float* __restrict__ out)
{
    __shared__ __align__(16) float s_znb[D];   // raw z_nb (pre-normalize)
    __shared__ float red2[32][2];
    __shared__ float s_acc[32][5];             // pad to 5: conflict-free
    __shared__ float s_om[FFN], s_ph[FFN];
    __shared__ float fr[3][32];
    __shared__ unsigned int s_islast;

    const int tid = threadIdx.x;
    const int lane = tid & 31, warp = tid >> 5;
    const int b = blockIdx.x;
    const float ct = cur_t[0];

    if (tid < FFN) { s_om[tid] = omega[tid]; s_ph[tid] = phi[tid]; }

    if (b < PP) {
        const int p = b;
        const int nbp = nbr_idxs[p];

        // ---- per-warp independent gather chain (issued ASAP) ----
        int idx = 0;
        if (lane == 0) idx = neighbors[nbp * DEGN + warp];
        idx = __shfl_sync(0xffffffffu, idx, 0);
        float et = 0.f;
        if (lane == 0) et = edge_times[(size_t)nbp * NN + idx];
        et = __shfl_sync(0xffffffffu, et, 0);
        float4 r   = ((const float4*)(z + (size_t)idx * D))[lane];
        float4 x   = ((const float4*)g_znx)[warp * 32 + lane];
        float4 zq4 = ((const float4*)g_zq)[lane];
        const float te_j = g_te[warp];

        // ---- first 128 threads: z_nb partial reductions (concurrent) ----
        if (tid < D) {
            float v  = z[(size_t)nbp * D + tid];
            float zq = g_zq[tid];
            float ss = warpSum(v * v);
            float dp = warpSum(v * zq);
            if (lane == 0) { red2[warp][0] = ss; red2[warp][1] = dp; }
            s_znb[tid] = v;
        }
        __syncthreads();

        const float SS = red2[0][0] + red2[1][0] + red2[2][0] + red2[3][0];
        const float invn = 1.f / fmaxf(sqrtf(SS), 1e-12f);
        float4 nb = ((const float4*)s_znb)[lane];
        nb.x *= invn; nb.y *= invn; nb.z *= invn; nb.w *= invn;

        // time encoding for (p, j): lane-parallel sinusoids
        const float dt = ct - et;
        float c = 0.f;
        if (lane == 0)       c = s_om[0] * dt + s_ph[0];
        else if (lane < FFN) c = sinf(s_om[lane] * dt + s_ph[lane]);

        // four independent butterflies
        float dot1 = warpSum(x.x*nb.x + x.y*nb.y + x.z*nb.z + x.w*nb.w);
        float ss2  = warpSum(r.x*r.x + r.y*r.y + r.z*r.z + r.w*r.w);
        float dot2 = warpSum(r.x*zq4.x + r.y*zq4.y + r.z*zq4.z + r.w*zq4.w);
        float te2  = warpSum(c);

        const float mu1 = 2.f * dot1 - 2.f;
        const float w1  = expf(mu1 * TEMP_INV - te_j);
        const float inv2 = 1.f / fmaxf(sqrtf(ss2), 1e-12f);
        const float mu2  = 2.f * dot2 * inv2 - 2.f;
        const float w2   = expf(mu2 * TEMP_INV - te2);

        if (lane == 0) {
            s_acc[warp][0] = w1;  s_acc[warp][1] = w1 * mu1;
            s_acc[warp][2] = w2;  s_acc[warp][3] = w2 * mu2;
        }
        __syncthreads();

        if (warp == 0) {
            float a0 = s_acc[lane][0], a1 = s_acc[lane][1];
            float a2 = s_acc[lane][2], a3 = s_acc[lane][3];
            a0 = warpSum(a0); a1 = warpSum(a1);
            a2 = warpSum(a2); a3 = warpSum(a3);
            if (lane == 0) {
                const float DP = red2[0][1] + red2[1][1] + red2[2][1] + red2[3][1];
                const float muxy = 2.f * DP * invn - 2.f;
                const float term1 = a1 / (a0 + 1e-8f);
                const float term2 = a3 / (a2 + 1e-8f);
                const float d = term1 + term2;         // lambda_T - lambda_S
                const float ad = fabsf(d);
                g_align_arr[p] = (ad < 1.f) ? 0.5f * d * d : ad - 0.5f;
                const float sgm = 1.f / (1.f + expf(-muxy));
                g_pos[p] = -logf(sgm + 1e-8f);
            }
        }
    } else {
        // ---- negative blocks: 8 negatives, one per 128-thread group ----
        const int grp = tid >> 7;          // 0..7
        const int gt  = tid & 127;
        const int k   = (b - PP) * 8 + grp;
        const int idx = neg_idxs[k];
        float v  = z[(size_t)idx * D + gt];
        float zq = g_zq[gt];
        float ss = warpSum(v * v);
        float dp = warpSum(v * zq);
        if (lane == 0) { red2[warp][0] = ss; red2[warp][1] = dp; }
        __syncthreads();
        if (gt == 0) {
            const int w0 = grp * 4;
            float SS = red2[w0][0] + red2[w0+1][0] + red2[w0+2][0] + red2[w0+3][0];
            float DP = red2[w0][1] + red2[w0+1][1] + red2[w0+2][1] + red2[w0+3][1];
            float mu  = 2.f * DP / fmaxf(sqrtf(SS), 1e-12f) - 2.f;
            float sgm = 1.f / (1.f + expf(-mu));
            g_neg[k] = -logf(1.f - sgm + 1e-8f);
        }
    }

    // ---- last-block final reduction (deterministic) ----
    __syncthreads();
    if (tid == 0) {
        __threadfence();
        unsigned int t = atomicAdd(&g_ctr, 1u);
        s_islast = (t == (unsigned int)(GRID - 1));
    }
    __syncthreads();
    if (s_islast) {
        float sp = (tid < PP) ? g_pos[tid]       : 0.f;
        float sa = (tid < PP) ? g_align_arr[tid] : 0.f;
        float sn = (tid < KK) ? g_neg[tid]       : 0.f;
        sp = warpSum(sp); sa = warpSum(sa); sn = warpSum(sn);
        if (lane == 0) { fr[0][warp] = sp; fr[1][warp] = sn; fr[2][warp] = sa; }
        __syncthreads();
        if (tid == 0) {
            float P = 0.f, Ng = 0.f, A = 0.f;
            for (int i = 0; i < 32; i++) {
                P += fr[0][i]; Ng += fr[1][i]; A += fr[2][i];
            }
            out[0] = P / PP + Ng / KK
                   + 0.1f * (g_core_sum / PP)
                   + 0.1f * (A / PP);
        }
    }
}

// ---------------------------------------------------------------------------
extern "C" void kernel_launch(void* const* d_in, const int* in_sizes, int n_in,
                              void* d_out, int out_size)
{
    const float* z          = (const float*)d_in[0];
    const float* edge_times = (const float*)d_in[1];
    const float* cur_t      = (const float*)d_in[2];
    const float* core       = (const float*)d_in[3];
    const float* omega      = (const float*)d_in[4];
    const float* phi        = (const float*)d_in[5];
    const int*   qidx       = (const int*)d_in[6];
    const int*   neg_idxs   = (const int*)d_in[7];
    const int*   nbr_idxs   = (const int*)d_in[8];
    const int*   neighbors  = (const int*)d_in[9];

    k0_setup<<<1, 1024>>>(z, edge_times, cur_t, core, omega, phi,
                          qidx, nbr_idxs, neighbors);
    k1_main<<<GRID, 1024>>>(z, edge_times, cur_t, omega, phi,
                            neg_idxs, nbr_idxs, neighbors, (float*)d_out);
}

// round 4
// speedup vs baseline: 2.6598x; 1.1841x over previous
#include <cuda_runtime.h>

// Shapes fixed by the dataset
#define NN   8192
#define D    128
#define PP   256
#define KK   256
#define DEGN 32
#define FFN  16
#define TEMP_INV (1.0f/0.07f)
#define NB_TERM (PP * 4)          // 4 quarter-blocks per p, 8 warps each
#define NB_NEG  (KK / 8)          // 8 negatives per block, one per warp
#define GRID    (NB_TERM + NB_NEG)

// Scratch (no allocations allowed)
__device__ float4 g_part4[PP * 4];   // [p][quarter] = {Sw1, Sw1mu1, Sw2, Sw2mu2}
__device__ float  g_pos[PP];
__device__ float  g_core[PP];
__device__ float  g_neg[KK];
__device__ unsigned int g_ctr;       // zero-init; last block resets to 0 each launch

__device__ __forceinline__ float warpSum(float v) {
#pragma unroll
    for (int o = 16; o; o >>= 1) v += __shfl_xor_sync(0xffffffffu, v, o);
    return v;
}
// sums independently within each 16-lane half
__device__ __forceinline__ float halfSum(float v) {
#pragma unroll
    for (int o = 8; o; o >>= 1) v += __shfl_xor_sync(0xffffffffu, v, o);
    return v;
}
__device__ __forceinline__ float dot4(float4 a, float4 b) {
    return a.x*b.x + a.y*b.y + a.z*b.z + a.w*b.w;
}

// ---------------------------------------------------------------------------
// Single fused kernel. Term blocks: b < NB_TERM, p = b>>2, quarter = b&3,
// warp w handles j = quarter*8 + w, fully warp-local (broadcast loads of the
// shared z[q] / z[nbp] rows). Neg blocks: one negative per warp.
// Last block to finish folds the final scalar reduction.
// ---------------------------------------------------------------------------
__global__ void __launch_bounds__(256)
k_all(const float* __restrict__ z,
      const float* __restrict__ edge_times,
      const float* __restrict__ cur_t,
      const float* __restrict__ core,
      const float* __restrict__ omega,
      const float* __restrict__ phi,
      const int*   __restrict__ qidx,
      const int*   __restrict__ neg_idxs,
      const int*   __restrict__ nbr_idxs,
      const int*   __restrict__ neighbors,
      float* __restrict__ out)
{
    __shared__ float4 s_acc[8];
    __shared__ float  s_fr[4][8];
    __shared__ unsigned int s_islast;

    const int tid  = threadIdx.x;
    const int lane = tid & 31, warp = tid >> 5;
    const int b    = blockIdx.x;
    const int q    = qidx[0];            // broadcast load
    const float ct = cur_t[0];

    if (b < NB_TERM) {
        const int p   = b >> 2;
        const int qtr = b & 3;
        const int j   = qtr * 8 + warp;
        const int nbp = nbr_idxs[p];                       // broadcast

        // depth-3 load chains (two independent), all broadcast within warp
        const int nqj  = neighbors[q   * DEGN + j];
        const int idx2 = neighbors[nbp * DEGN + j];
        const float etq = edge_times[(size_t)q   * NN + nqj];
        const float ety = edge_times[(size_t)nbp * NN + idx2];

        const float4 x  = ((const float4*)(z + (size_t)nqj  * D))[lane];
        const float4 r  = ((const float4*)(z + (size_t)idx2 * D))[lane];
        const float4 zq = ((const float4*)(z + (size_t)q    * D))[lane];
        const float4 vb = ((const float4*)(z + (size_t)nbp  * D))[lane];

        // time encodings: lanes 0-15 -> query side (dt1), 16-31 -> neighbor side
        const int   f  = lane & 15;
        const float dt = (lane < 16) ? (ct - etq) : (ct - ety);
        float c = (f == 0) ? (omega[0] * dt + phi[0])
                           : sinf(omega[f] * dt + phi[f]);

        // independent butterflies (ILP-overlapped)
        float ssx = warpSum(dot4(x, x));
        float ssr = warpSum(dot4(r, r));
        float ssq = warpSum(dot4(zq, zq));
        float ssb = warpSum(dot4(vb, vb));
        float d1  = warpSum(dot4(x, vb));
        float d2  = warpSum(dot4(r, zq));
        float hc  = halfSum(c);
        const float te1 = __shfl_sync(0xffffffffu, hc, 0);
        const float te2 = __shfl_sync(0xffffffffu, hc, 16);

        const float mu1 = 2.f * d1 * rsqrtf(ssx * ssb) - 2.f;
        const float w1  = expf(mu1 * TEMP_INV - te1);
        const float mu2 = 2.f * d2 * rsqrtf(ssr * ssq) - 2.f;
        const float w2  = expf(mu2 * TEMP_INV - te2);

        if (lane == 0) s_acc[warp] = make_float4(w1, w1 * mu1, w2, w2 * mu2);

        // quarter 0, warp 0 additionally emits pos-loss and core term for p
        if (qtr == 0 && warp == 0) {
            float dqb = warpSum(dot4(vb, zq));
            if (lane == 0) {
                float muxy = 2.f * dqb * rsqrtf(ssb * ssq) - 2.f;
                float sgm  = 1.f / (1.f + expf(-muxy));
                g_pos[p] = -logf(sgm + 1e-8f);
                float cd = core[nbp] - core[q];
                g_core[p] = cd * cd;
            }
        }
        __syncthreads();

        if (warp == 0) {
            float4 a = (lane < 8) ? s_acc[lane] : make_float4(0.f, 0.f, 0.f, 0.f);
            a.x = warpSum(a.x); a.y = warpSum(a.y);
            a.z = warpSum(a.z); a.w = warpSum(a.w);
            if (lane == 0) g_part4[p * 4 + qtr] = a;
        }
    } else {
        // negative blocks: warp w handles negative k
        const int k  = (b - NB_TERM) * 8 + warp;
        const int nk = neg_idxs[k];                        // broadcast
        const float4 v  = ((const float4*)(z + (size_t)nk * D))[lane];
        const float4 zq = ((const float4*)(z + (size_t)q  * D))[lane];
        float ssv = warpSum(dot4(v, v));
        float ssq = warpSum(dot4(zq, zq));
        float dv  = warpSum(dot4(v, zq));
        if (lane == 0) {
            float mu  = 2.f * dv * rsqrtf(ssv * ssq) - 2.f;
            float sgm = 1.f / (1.f + expf(-mu));
            g_neg[k] = -logf(1.f - sgm + 1e-8f);
        }
    }

    // ---- last-block final reduction (deterministic) ----
    __syncthreads();
    if (tid == 0) {
        __threadfence();
        unsigned int t = atomicAdd(&g_ctr, 1u);
        s_islast = (t == (unsigned int)(GRID - 1));
    }
    __syncthreads();
    if (s_islast) {
        // thread tid owns p = tid (and neg k = tid)
        float4 q0 = g_part4[tid * 4 + 0];
        float4 q1 = g_part4[tid * 4 + 1];
        float4 q2 = g_part4[tid * 4 + 2];
        float4 q3 = g_part4[tid * 4 + 3];
        float W1  = q0.x + q1.x + q2.x + q3.x;
        float WM1 = q0.y + q1.y + q2.y + q3.y;
        float W2  = q0.z + q1.z + q2.z + q3.z;
        float WM2 = q0.w + q1.w + q2.w + q3.w;
        float term1 = WM1 / (W1 + 1e-8f);
        float term2 = WM2 / (W2 + 1e-8f);
        float d  = term1 + term2;            // lambda_T - lambda_S
        float ad = fabsf(d);
        float al = (ad < 1.f) ? 0.5f * d * d : ad - 0.5f;

        float a  = warpSum(al);
        float sp = warpSum(g_pos[tid]);
        float sc = warpSum(g_core[tid]);
        float sn = warpSum(g_neg[tid]);
        if (lane == 0) {
            s_fr[0][warp] = a;  s_fr[1][warp] = sp;
            s_fr[2][warp] = sc; s_fr[3][warp] = sn;
        }
        __syncthreads();
        if (tid == 0) {
            float A = 0.f, P = 0.f, C = 0.f, Ng = 0.f;
#pragma unroll
            for (int i = 0; i < 8; i++) {
                A += s_fr[0][i]; P += s_fr[1][i];
                C += s_fr[2][i]; Ng += s_fr[3][i];
            }
            out[0] = P / PP + Ng / KK
                   + 0.1f * (C / PP)
                   + 0.1f * (A / PP);
            g_ctr = 0;    // reset for next graph replay
        }
    }
}

// ---------------------------------------------------------------------------
extern "C" void kernel_launch(void* const* d_in, const int* in_sizes, int n_in,
                              void* d_out, int out_size)
{
    const float* z          = (const float*)d_in[0];
    const float* edge_times = (const float*)d_in[1];
    const float* cur_t      = (const float*)d_in[2];
    const float* core       = (const float*)d_in[3];
    const float* omega      = (const float*)d_in[4];
    const float* phi        = (const float*)d_in[5];
    const int*   qidx       = (const int*)d_in[6];
    const int*   neg_idxs   = (const int*)d_in[7];
    const int*   nbr_idxs   = (const int*)d_in[8];
    const int*   neighbors  = (const int*)d_in[9];

    k_all<<<GRID, 256>>>(z, edge_times, cur_t, core, omega, phi,
                         qidx, neg_idxs, nbr_idxs, neighbors, (float*)d_out);
}